// round 13
// baseline (speedup 1.0000x reference)
#include <cuda_runtime.h>
#include <math.h>

// Shape-specialized for this problem instance.
#define HF 37
#define WF 50
#define CH 512
#define C4 (CH / 4)          // 128 float4 per pixel
#define POOL 7
#define CELLS (POOL * POOL)  // 49
#define SAMP 14
#define NMAX 1024
#define ROWSTRIDE (WF * C4)

// Per-(roi, sample) descriptors: {floor_index, bitcast(frac_weight)}.
// Pairs (2p, 2p+1) are contiguous and 16B-aligned -> single int4 load per axis.
__device__ int2 g_ydesc[NMAX * SAMP];
__device__ int2 g_xdesc[NMAX * SAMP];

__global__ void setup_kernel(const float* __restrict__ rois,
                             const int* __restrict__ im, int n) {
    const int i = blockIdx.x * blockDim.x + threadIdx.x;
    if (i >= n * SAMP) return;
    const int roi = i / SAMP;
    const int s   = i - roi * SAMP;

    const float hinv = 1.0f / (float)im[0];
    const float winv = 1.0f / (float)im[1];
    const float t = (float)s * (1.0f / 13.0f);

    const float ny1 = rois[roi * 4 + 1] * hinv;
    const float ny2 = rois[roi * 4 + 3] * hinv;
    float y = (ny1 + (ny2 - ny1) * t) * (float)(HF - 1);
    y = fminf(fmaxf(y, 0.0f), (float)(HF - 1));
    const float y0f = floorf(y);
    g_ydesc[i] = make_int2((int)y0f, __float_as_int(y - y0f));

    const float nx1 = rois[roi * 4 + 0] * winv;
    const float nx2 = rois[roi * 4 + 2] * winv;
    float x = (nx1 + (nx2 - nx1) * t) * (float)(WF - 1);
    x = fminf(fmaxf(x, 0.0f), (float)(WF - 1));
    const float x0f = floorf(x);
    g_xdesc[i] = make_int2((int)x0f, __float_as_int(x - x0f));
}

__device__ __forceinline__ float4 lerp4(const float4 a, const float4 b, const float w) {
    return make_float4(fmaf(w, b.x - a.x, a.x),
                       fmaf(w, b.y - a.y, a.y),
                       fmaf(w, b.z - a.z, a.z),
                       fmaf(w, b.w - a.w, a.w));
}

__device__ __forceinline__ void max4(float4& acc, const float4 v) {
    acc.x = fmaxf(acc.x, v.x);
    acc.y = fmaxf(acc.y, v.y);
    acc.z = fmaxf(acc.z, v.z);
    acc.w = fmaxf(acc.w, v.w);
}

// Load one feature column c and reduce it immediately to the two y-lerped
// values (v0 for y-sample 0, v1 for y-sample 1). NL = pixel loads per column:
//   NL=2 (dy==0):  rows {r0,r1};           v0=lerp(p0,p1,wy0) v1=lerp(p0,p1,wy1)
//   NL=3 (dy==1):  rows {r0,r1,r2};        v0=lerp(p0,p1,wy0) v1=lerp(p1,p2,wy1)
//   NL=4 (dy>=2):  rows {r0,r1,r2,r3};     v0=lerp(p0,p1,wy0) v1=lerp(p2,p3,wy1)
template<int NL>
__device__ __forceinline__ void load_col(const float4* __restrict__ r0,
                                         const float4* __restrict__ r1,
                                         const float4* __restrict__ r2,
                                         const float4* __restrict__ r3,
                                         const int c,
                                         const float wy0, const float wy1,
                                         float4& v0, float4& v1) {
    const int o = c * C4;
    const float4 p0 = __ldg(r0 + o);
    const float4 p1 = __ldg(r1 + o);
    v0 = lerp4(p0, p1, wy0);
    if (NL == 2) {
        v1 = lerp4(p0, p1, wy1);
    } else if (NL == 3) {
        const float4 p2 = __ldg(r2 + o);
        v1 = lerp4(p1, p2, wy1);
    } else {
        const float4 p2 = __ldg(r2 + o);
        const float4 p3 = __ldg(r3 + o);
        v1 = lerp4(p2, p3, wy1);
    }
}

// Stream one pooled row (7 cells, 14 monotone x-samples) with a sliding
// 2-column window of y-lerped values: state A0,A1 (col cc) / B0,B1 (col cc+1).
// Each distinct column is loaded exactly once.
template<int NL>
__device__ __forceinline__ void row_stream(const float4* __restrict__ r0,
                                           const float4* __restrict__ r1,
                                           const float4* __restrict__ r2,
                                           const float4* __restrict__ r3,
                                           float4* __restrict__ ob,
                                           const float wy0, const float wy1,
                                           const int2* __restrict__ xdp)
{
    int cc = __ldg(&xdp[0].x);
    float4 A0, A1, B0, B1;
    load_col<NL>(r0, r1, r2, r3, cc, wy0, wy1, A0, A1);
    load_col<NL>(r0, r1, r2, r3, min(cc + 1, WF - 1), wy0, wy1, B0, B1);

    #pragma unroll 1
    for (int px = 0; px < POOL; ++px) {
        const int4 xd = __ldg((const int4*)(xdp + 2 * px));
        float4 acc = make_float4(-INFINITY, -INFINITY, -INFINITY, -INFINITY);

        #pragma unroll
        for (int h = 0; h < 2; ++h) {
            const int   x0 = h ? xd.z : xd.x;
            const float wx = __int_as_float(h ? xd.w : xd.y);

            while (cc < x0) {           // warp-uniform advance
                ++cc;
                A0 = B0; A1 = B1;
                load_col<NL>(r0, r1, r2, r3, min(cc + 1, WF - 1),
                             wy0, wy1, B0, B1);
            }

            max4(acc, lerp4(A0, B0, wx));
            max4(acc, lerp4(A1, B1, wx));
        }

        ob[px * C4] = acc;
    }
}

__global__ __launch_bounds__(C4, 10)
void roipool_kernel(const float4* __restrict__ feat,   // [HF*WF, C4]
                    float4* __restrict__ out)          // [N*49, C4]
{
    const int blk = blockIdx.x;
    const int roi = blk / POOL;
    const int py  = blk - roi * POOL;
    const int tid = threadIdx.x;

    const int4 yd = __ldg((const int4*)&g_ydesc[roi * SAMP + 2 * py]);
    const int y0a = yd.x, y0b = yd.z;
    const float wy0 = __int_as_float(yd.y);
    const float wy1 = __int_as_float(yd.w);
    const int dy = y0b - y0a;   // >= 0 (samples are monotone)

    const float4* fb  = feat + tid;   // per-thread channel base
    float4*       ob  = out + (size_t)(roi * CELLS + py * POOL) * C4 + tid;
    const int2*   xdp = &g_xdesc[roi * SAMP];

    const float4* r0 = fb + y0a * ROWSTRIDE;
    const float4* r1 = fb + min(y0a + 1, HF - 1) * ROWSTRIDE;

    if (dy == 0) {
        row_stream<2>(r0, r1, r1, r1, ob, wy0, wy1, xdp);
    } else if (dy == 1) {
        const float4* r2 = fb + min(y0a + 2, HF - 1) * ROWSTRIDE;
        row_stream<3>(r0, r1, r2, r2, ob, wy0, wy1, xdp);
    } else {
        const float4* r2 = fb + y0b * ROWSTRIDE;
        const float4* r3 = fb + min(y0b + 1, HF - 1) * ROWSTRIDE;
        row_stream<4>(r0, r1, r2, r3, ob, wy0, wy1, xdp);
    }
}

extern "C" void kernel_launch(void* const* d_in, const int* in_sizes, int n_in,
                              void* d_out, int out_size) {
    const float4* feat = (const float4*)d_in[0];
    const float*  rois = (const float*)d_in[1];
    const int*    im   = (const int*)d_in[2];
    float4*       out  = (float4*)d_out;

    const int n = in_sizes[1] / 4;   // number of rois

    const int setup_threads = n * SAMP;
    setup_kernel<<<(setup_threads + 127) / 128, 128>>>(rois, im, n);
    roipool_kernel<<<n * POOL, C4>>>(feat, out);
}

// round 16
// speedup vs baseline: 2.1258x; 2.1258x over previous
#include <cuda_runtime.h>
#include <math.h>

// Shape-specialized for this problem instance.
#define HF 37
#define WF 50
#define CH 512
#define C4 (CH / 4)          // 128 float4 per pixel
#define POOL 7
#define CELLS (POOL * POOL)  // 49
#define SAMP 14
#define NMAX 1024
#define ROWSTRIDE (WF * C4)

// Per-(roi, sample) descriptors: {floor_index, bitcast(frac_weight)}.
// Pairs (2p, 2p+1) are contiguous and 16B-aligned -> single int4 load per axis.
__device__ int2 g_ydesc[NMAX * SAMP];
__device__ int2 g_xdesc[NMAX * SAMP];

__global__ void setup_kernel(const float* __restrict__ rois,
                             const int* __restrict__ im, int n) {
    const int i = blockIdx.x * blockDim.x + threadIdx.x;
    if (i >= n * SAMP) return;
    const int roi = i / SAMP;
    const int s   = i - roi * SAMP;

    const float hinv = 1.0f / (float)im[0];
    const float winv = 1.0f / (float)im[1];
    const float t = (float)s * (1.0f / 13.0f);

    const float ny1 = rois[roi * 4 + 1] * hinv;
    const float ny2 = rois[roi * 4 + 3] * hinv;
    float y = (ny1 + (ny2 - ny1) * t) * (float)(HF - 1);
    y = fminf(fmaxf(y, 0.0f), (float)(HF - 1));
    const float y0f = floorf(y);
    g_ydesc[i] = make_int2((int)y0f, __float_as_int(y - y0f));

    const float nx1 = rois[roi * 4 + 0] * winv;
    const float nx2 = rois[roi * 4 + 2] * winv;
    float x = (nx1 + (nx2 - nx1) * t) * (float)(WF - 1);
    x = fminf(fmaxf(x, 0.0f), (float)(WF - 1));
    const float x0f = floorf(x);
    g_xdesc[i] = make_int2((int)x0f, __float_as_int(x - x0f));
}

__device__ __forceinline__ float4 lerp4(const float4 a, const float4 b, const float w) {
    return make_float4(fmaf(w, b.x - a.x, a.x),
                       fmaf(w, b.y - a.y, a.y),
                       fmaf(w, b.z - a.z, a.z),
                       fmaf(w, b.w - a.w, a.w));
}

__device__ __forceinline__ void max4(float4& acc, const float4 v) {
    acc.x = fmaxf(acc.x, v.x);
    acc.y = fmaxf(acc.y, v.y);
    acc.z = fmaxf(acc.z, v.z);
    acc.w = fmaxf(acc.w, v.w);
}

// Load one feature column c and reduce it immediately to the two y-lerped
// values (v0 for y-sample 0, v1 for y-sample 1). NL = pixel loads per column:
//   NL=2 (dy==0):  rows {r0,r1};        v0=lerp(p0,p1,wy0)  v1=lerp(p0,p1,wy1)
//   NL=3 (dy==1):  rows {r0,r1,r2};     v0=lerp(p0,p1,wy0)  v1=lerp(p1,p2,wy1)
//   NL=4 (dy>=2):  rows {r0,r1,r2,r3};  v0=lerp(p0,p1,wy0)  v1=lerp(p2,p3,wy1)
template<int NL>
__device__ __forceinline__ void load_col(const float4* __restrict__ r0,
                                         const float4* __restrict__ r1,
                                         const float4* __restrict__ r2,
                                         const float4* __restrict__ r3,
                                         const int c,
                                         const float wy0, const float wy1,
                                         float4& v0, float4& v1) {
    const int o = c * C4;
    const float4 p0 = __ldg(r0 + o);
    const float4 p1 = __ldg(r1 + o);
    v0 = lerp4(p0, p1, wy0);
    if (NL == 2) {
        v1 = lerp4(p0, p1, wy1);
    } else if (NL == 3) {
        const float4 p2 = __ldg(r2 + o);
        v1 = lerp4(p1, p2, wy1);
    } else {
        const float4 p2 = __ldg(r2 + o);
        const float4 p3 = __ldg(r3 + o);
        v1 = lerp4(p2, p3, wy1);
    }
}

// Stream one pooled row (7 cells, 14 monotone x-samples) with a sliding
// 2-column window of y-lerped values: state A0,A1 (col cc) / B0,B1 (col cc+1).
// Each distinct column is loaded exactly once.
template<int NL>
__device__ __forceinline__ void row_stream(const float4* __restrict__ r0,
                                           const float4* __restrict__ r1,
                                           const float4* __restrict__ r2,
                                           const float4* __restrict__ r3,
                                           float4* __restrict__ ob,
                                           const float wy0, const float wy1,
                                           const int2* __restrict__ xdp)
{
    int cc = __ldg(&xdp[0].x);
    float4 A0, A1, B0, B1;
    load_col<NL>(r0, r1, r2, r3, cc, wy0, wy1, A0, A1);
    load_col<NL>(r0, r1, r2, r3, min(cc + 1, WF - 1), wy0, wy1, B0, B1);

    #pragma unroll 1
    for (int px = 0; px < POOL; ++px) {
        const int4 xd = __ldg((const int4*)(xdp + 2 * px));
        float4 acc = make_float4(-INFINITY, -INFINITY, -INFINITY, -INFINITY);

        #pragma unroll
        for (int h = 0; h < 2; ++h) {
            const int   x0 = h ? xd.z : xd.x;
            const float wx = __int_as_float(h ? xd.w : xd.y);

            while (cc < x0) {           // warp-uniform advance
                ++cc;
                A0 = B0; A1 = B1;
                load_col<NL>(r0, r1, r2, r3, min(cc + 1, WF - 1),
                             wy0, wy1, B0, B1);
            }

            max4(acc, lerp4(A0, B0, wx));
            max4(acc, lerp4(A1, B1, wx));
        }

        ob[px * C4] = acc;
    }
}

__global__ __launch_bounds__(C4)
void roipool_kernel(const float4* __restrict__ feat,   // [HF*WF, C4]
                    float4* __restrict__ out)          // [N*49, C4]
{
    const int blk = blockIdx.x;
    const int roi = blk / POOL;
    const int py  = blk - roi * POOL;
    const int tid = threadIdx.x;

    const int4 yd = __ldg((const int4*)&g_ydesc[roi * SAMP + 2 * py]);
    const int y0a = yd.x, y0b = yd.z;
    const float wy0 = __int_as_float(yd.y);
    const float wy1 = __int_as_float(yd.w);
    const int dy = y0b - y0a;   // >= 0 (samples are monotone)

    const float4* fb  = feat + tid;   // per-thread channel base
    float4*       ob  = out + (size_t)(roi * CELLS + py * POOL) * C4 + tid;
    const int2*   xdp = &g_xdesc[roi * SAMP];

    const float4* r0 = fb + y0a * ROWSTRIDE;
    const float4* r1 = fb + min(y0a + 1, HF - 1) * ROWSTRIDE;

    if (dy == 0) {
        row_stream<2>(r0, r1, r1, r1, ob, wy0, wy1, xdp);
    } else if (dy == 1) {
        const float4* r2 = fb + min(y0a + 2, HF - 1) * ROWSTRIDE;
        row_stream<3>(r0, r1, r2, r2, ob, wy0, wy1, xdp);
    } else {
        const float4* r2 = fb + y0b * ROWSTRIDE;
        const float4* r3 = fb + min(y0b + 1, HF - 1) * ROWSTRIDE;
        row_stream<4>(r0, r1, r2, r3, ob, wy0, wy1, xdp);
    }
}

extern "C" void kernel_launch(void* const* d_in, const int* in_sizes, int n_in,
                              void* d_out, int out_size) {
    const float4* feat = (const float4*)d_in[0];
    const float*  rois = (const float*)d_in[1];
    const int*    im   = (const int*)d_in[2];
    float4*       out  = (float4*)d_out;

    const int n = in_sizes[1] / 4;   // number of rois

    const int setup_threads = n * SAMP;
    setup_kernel<<<(setup_threads + 127) / 128, 128>>>(rois, im, n);
    roipool_kernel<<<n * POOL, C4>>>(feat, out);
}

// round 17
// speedup vs baseline: 3.7291x; 1.7542x over previous
#include <cuda_runtime.h>
#include <math.h>

// Shape-specialized for this problem instance.
#define HF 37
#define WF 50
#define CH 512
#define C4 (CH / 4)          // 128 float4 per pixel
#define POOL 7
#define CELLS (POOL * POOL)  // 49
#define SAMP 14
#define NMAX 1024
#define ROWSTRIDE (WF * C4)

// Per-(roi, sample) descriptors: {floor_index, bitcast(frac_weight)}.
// Pairs (2p, 2p+1) are contiguous and 16B-aligned -> single int4 load per axis.
__device__ int2 g_ydesc[NMAX * SAMP];
__device__ int2 g_xdesc[NMAX * SAMP];

__global__ void setup_kernel(const float* __restrict__ rois,
                             const int* __restrict__ im, int n) {
    const int i = blockIdx.x * blockDim.x + threadIdx.x;
    if (i >= n * SAMP) return;
    const int roi = i / SAMP;
    const int s   = i - roi * SAMP;

    const float hinv = 1.0f / (float)im[0];
    const float winv = 1.0f / (float)im[1];
    const float t = (float)s * (1.0f / 13.0f);

    const float ny1 = rois[roi * 4 + 1] * hinv;
    const float ny2 = rois[roi * 4 + 3] * hinv;
    float y = (ny1 + (ny2 - ny1) * t) * (float)(HF - 1);
    y = fminf(fmaxf(y, 0.0f), (float)(HF - 1));
    const float y0f = floorf(y);
    g_ydesc[i] = make_int2((int)y0f, __float_as_int(y - y0f));

    const float nx1 = rois[roi * 4 + 0] * winv;
    const float nx2 = rois[roi * 4 + 2] * winv;
    float x = (nx1 + (nx2 - nx1) * t) * (float)(WF - 1);
    x = fminf(fmaxf(x, 0.0f), (float)(WF - 1));
    const float x0f = floorf(x);
    g_xdesc[i] = make_int2((int)x0f, __float_as_int(x - x0f));
}

__device__ __forceinline__ void bmax(float4& acc,
                                     const float4 a, const float4 b,
                                     const float4 c, const float4 d,
                                     const float wy, const float wx) {
    const float w00 = (1.0f - wy) * (1.0f - wx);
    const float w01 = (1.0f - wy) * wx;
    const float w10 = wy * (1.0f - wx);
    const float w11 = wy * wx;
    acc.x = fmaxf(acc.x, a.x * w00 + b.x * w01 + c.x * w10 + d.x * w11);
    acc.y = fmaxf(acc.y, a.y * w00 + b.y * w01 + c.y * w10 + d.y * w11);
    acc.z = fmaxf(acc.z, a.z * w00 + b.z * w01 + c.z * w10 + d.z * w11);
    acc.w = fmaxf(acc.w, a.w * w00 + b.w * w01 + c.w * w10 + d.w * w11);
}

// R8-proven fast path: the 4 samples' corner pixels form a (2+DY)x(2+DX)
// rectangle at (R0, C0). Each distinct pixel loaded exactly once; boundary
// clamping folded into the load indices. All state is transient.
template<int DY, int DX>
__device__ __forceinline__ float4 cell_fast(const float4* __restrict__ fb,
                                            const int R0, const int C0,
                                            const float* wyv, const float* wxv) {
    float4 P[2 + DY][2 + DX];
    #pragma unroll
    for (int i = 0; i < 2 + DY; ++i) {
        const int r = min(R0 + i, HF - 1);
        #pragma unroll
        for (int j = 0; j < 2 + DX; ++j) {
            const int c = min(C0 + j, WF - 1);
            P[i][j] = __ldg(&fb[(r * WF + c) * C4]);
        }
    }
    float4 acc = make_float4(-INFINITY, -INFINITY, -INFINITY, -INFINITY);
    #pragma unroll
    for (int sy = 0; sy < 2; ++sy) {
        #pragma unroll
        for (int sx = 0; sx < 2; ++sx) {
            bmax(acc,
                 P[sy * DY    ][sx * DX    ],
                 P[sy * DY    ][sx * DX + 1],
                 P[sy * DY + 1][sx * DX    ],
                 P[sy * DY + 1][sx * DX + 1],
                 wyv[sy], wxv[sx]);
        }
    }
    return acc;
}

// One x-sample (cols C0, C0+1) against both y-samples. For the rare dx>=2
// case; called once per x-sample.
template<int DY>
__device__ __forceinline__ void half_cell(float4& acc,
                                          const float4* __restrict__ fb,
                                          const int R0, const int C0,
                                          const float* wyv, const float wx) {
    float4 P[2 + DY][2];
    #pragma unroll
    for (int i = 0; i < 2 + DY; ++i) {
        const int r = min(R0 + i, HF - 1);
        #pragma unroll
        for (int j = 0; j < 2; ++j) {
            const int c = min(C0 + j, WF - 1);
            P[i][j] = __ldg(&fb[(r * WF + c) * C4]);
        }
    }
    #pragma unroll
    for (int sy = 0; sy < 2; ++sy) {
        bmax(acc, P[sy * DY][0], P[sy * DY][1],
                  P[sy * DY + 1][0], P[sy * DY + 1][1], wyv[sy], wx);
    }
}

// Loop over the 7 cells of one pooled row; y-descriptor fixed (DY known).
// Consecutive cells overlap in feature columns -> L1 hits.
template<int DY>
__device__ __forceinline__ void row_loop(const float4* __restrict__ fb,
                                         float4* __restrict__ ob,
                                         const int R0, const float* wyv,
                                         const int2* __restrict__ xdp) {
    #pragma unroll 1
    for (int px = 0; px < POOL; ++px) {
        const int4 xd = __ldg((const int4*)(xdp + 2 * px));
        const int x0a = xd.x, x0b = xd.z;
        const float wxv[2] = { __int_as_float(xd.y), __int_as_float(xd.w) };
        const int dx = x0b - x0a;

        float4 acc;
        if (dx == 0) {
            acc = cell_fast<DY, 0>(fb, R0, x0a, wyv, wxv);
        } else if (dx == 1) {
            acc = cell_fast<DY, 1>(fb, R0, x0a, wyv, wxv);
        } else {
            acc = make_float4(-INFINITY, -INFINITY, -INFINITY, -INFINITY);
            half_cell<DY>(acc, fb, R0, x0a, wyv, wxv[0]);
            half_cell<DY>(acc, fb, R0, x0b, wyv, wxv[1]);
        }
        ob[px * C4] = acc;
    }
}

__global__ __launch_bounds__(C4)
void roipool_kernel(const float4* __restrict__ feat,   // [HF*WF, C4]
                    float4* __restrict__ out)          // [N*49, C4]
{
    const int blk = blockIdx.x;
    const int roi = blk / POOL;
    const int py  = blk - roi * POOL;
    const int tid = threadIdx.x;

    const int4 yd = __ldg((const int4*)&g_ydesc[roi * SAMP + 2 * py]);
    const int y0a = yd.x, y0b = yd.z;
    const float wyv[2] = { __int_as_float(yd.y), __int_as_float(yd.w) };
    const int dy = y0b - y0a;   // >= 0 (samples are monotone)

    const float4* fb  = feat + tid;   // per-thread channel base
    float4*       ob  = out + (size_t)(roi * CELLS + py * POOL) * C4 + tid;
    const int2*   xdp = &g_xdesc[roi * SAMP];

    if (dy == 0) {
        row_loop<0>(fb, ob, y0a, wyv, xdp);
    } else if (dy == 1) {
        row_loop<1>(fb, ob, y0a, wyv, xdp);
    } else {
        // Rare dy>=2: per-cell 16-load path, transient state only.
        const int ri[2][2] = { { y0a, min(y0a + 1, HF - 1) },
                               { y0b, min(y0b + 1, HF - 1) } };
        #pragma unroll 1
        for (int px = 0; px < POOL; ++px) {
            const int4 xd = __ldg((const int4*)(xdp + 2 * px));
            const int x0i[2] = { xd.x, xd.z };
            const float wxv[2] = { __int_as_float(xd.y), __int_as_float(xd.w) };

            float4 acc = make_float4(-INFINITY, -INFINITY, -INFINITY, -INFINITY);
            #pragma unroll
            for (int sy = 0; sy < 2; ++sy) {
                #pragma unroll
                for (int sx = 0; sx < 2; ++sx) {
                    const int c0 = x0i[sx];
                    const int c1 = min(c0 + 1, WF - 1);
                    const float4 a = __ldg(&fb[(ri[sy][0] * WF + c0) * C4]);
                    const float4 b = __ldg(&fb[(ri[sy][0] * WF + c1) * C4]);
                    const float4 c = __ldg(&fb[(ri[sy][1] * WF + c0) * C4]);
                    const float4 d = __ldg(&fb[(ri[sy][1] * WF + c1) * C4]);
                    bmax(acc, a, b, c, d, wyv[sy], wxv[sx]);
                }
            }
            ob[px * C4] = acc;
        }
    }
}

extern "C" void kernel_launch(void* const* d_in, const int* in_sizes, int n_in,
                              void* d_out, int out_size) {
    const float4* feat = (const float4*)d_in[0];
    const float*  rois = (const float*)d_in[1];
    const int*    im   = (const int*)d_in[2];
    float4*       out  = (float4*)d_out;

    const int n = in_sizes[1] / 4;   // number of rois

    const int setup_threads = n * SAMP;
    setup_kernel<<<(setup_threads + 127) / 128, 128>>>(rois, im, n);
    roipool_kernel<<<n * POOL, C4>>>(feat, out);
}